// round 4
// baseline (speedup 1.0000x reference)
#include <cuda_runtime.h>
#include <math.h>

#define ANG   7
#define NV    49
#define HH    256
#define WW    256
#define BB    4
#define CROPP 8
#define CH    (HH - 2*CROPP)   // 240
#define CW    (WW - 2*CROPP)   // 240
#define HW3   (HH*WW*3)
#define VIEW_STRIDE HW3
#define BATCH_STRIDE (NV*HW3)
#define NBLOCKS 1800

__device__ float g_cl_part[NBLOCKS];
__device__ float g_gx_part[NBLOCKS];
__device__ float g_gy_part[NBLOCKS];
__device__ int   g_dummy;

__global__ void dummy_kernel() {
    if (threadIdx.x == 0 && blockIdx.x == 0) g_dummy = 0;
}

// ---------------------------------------------------------------------------
// Fused kernel: one thread per cropped pixel (b, py, px).
//  - bilinear warp of 49 views, cl[n] -> shared memory
//  - edge-aware smoothness terms (fused, same pixel domain)
//  - angular 3x3 gaussian (rolling 3 rows from smem)
//  - rank-count top-m exclusion, masked sum
//  - block partials to per-block slots (no atomics, no zero pass)
// ---------------------------------------------------------------------------
__global__ __launch_bounds__(128, 4)
void color_kernel(const float* __restrict__ pred,
                  const float* __restrict__ x,
                  const float* __restrict__ y,
                  const int*   __restrict__ epoch)
{
    __shared__ float scl[NV * 128];    // cl values, [n*128 + tid], conflict-free

    const int tid = threadIdx.x;
    const int idx = blockIdx.x * 128 + tid;       // exact grid, no tail
    const int px  = (idx % CW) + CROPP;
    const int py  = ((idx / CW) % CH) + CROPP;
    const int b   = idx / (CH * CW);

    const float* pr = pred + b * HH * WW;
    const float  p  = pr[py * WW + px];
    const float* xb = x + (size_t)b * BATCH_STRIDE;

    // ---- per-offset coordinate precompute (du/dv share the same 7 offsets)
    int   yo0[7], yo1[7], xo0[7], xo1[7];
    float ta[7], tb[7];
#pragma unroll
    for (int k = 0; k < 7; ++k) {
        const float off = (float)(k - 3);
        float cy = fminf(fmaxf((float)py + p * off, 0.0f), (float)(HH - 1));
        float fy = floorf(cy);
        int   y0 = (int)fy;
        ta[k]  = cy - fy;
        yo0[k] = y0 * (WW * 3);
        yo1[k] = min(y0 + 1, HH - 1) * (WW * 3);

        float cx = fminf(fmaxf((float)px + p * off, 0.0f), (float)(WW - 1));
        float fx = floorf(cx);
        int   x0 = (int)fx;
        tb[k]  = cx - fx;
        xo0[k] = x0 * 3;
        xo1[k] = min(x0 + 1, WW - 1) * 3;
    }

    // ---- center view pixel (view 24 warps to identity at its own pixel)
    const float* Icen = xb + 24 * VIEW_STRIDE;
    const int co = py * (WW * 3) + px * 3;
    const float cen0 = Icen[co + 0];
    const float cen1 = Icen[co + 1];
    const float cen2 = Icen[co + 2];

    // ---- fused edge-aware smoothness terms (uses center view + pred)
    float gx_t = 0.0f, gy_t = 0.0f;
    {
        const int cx = px - CROPP, ry = py - CROPP;
        if (cx < CW - 1) {
            float a = fabsf(Icen[co + 3] - cen0)
                    + fabsf(Icen[co + 4] - cen1)
                    + fabsf(Icen[co + 5] - cen2);
            float wx = expf(-150.0f * a * (1.0f / 3.0f));
            gx_t = wx * fabsf(pr[py * WW + px + 1] - p);
        }
        if (ry < CH - 1) {
            float a = fabsf(Icen[co + WW * 3 + 0] - cen0)
                    + fabsf(Icen[co + WW * 3 + 1] - cen1)
                    + fabsf(Icen[co + WW * 3 + 2] - cen2);
            float wy = expf(-150.0f * a * (1.0f / 3.0f));
            gy_t = wy * fabsf(pr[(py + 1) * WW + px] - p);
        }
    }

    // ---- bilinear warp + color loss per view -> shared
    float total = 0.0f;
#pragma unroll
    for (int n = 0; n < NV; ++n) {
        const int du = n / 7, dv = n % 7;
        const float* base = xb + n * VIEW_STRIDE;
        const float* p00 = base + yo0[du] + xo0[dv];
        const float* p01 = base + yo0[du] + xo1[dv];
        const float* p10 = base + yo1[du] + xo0[dv];
        const float* p11 = base + yo1[du] + xo1[dv];
        const float ty = ta[du], tx = tb[dv];
        const float w00 = (1.0f - ty) * (1.0f - tx);
        const float w01 = (1.0f - ty) * tx;
        const float w10 = ty * (1.0f - tx);
        const float w11 = ty * tx;

        float v0 = w00 * p00[0] + w01 * p01[0] + w10 * p10[0] + w11 * p11[0];
        float v1 = w00 * p00[1] + w01 * p01[1] + w10 * p10[1] + w11 * p11[1];
        float v2 = w00 * p00[2] + w01 * p01[2] + w10 * p10[2] + w11 * p11[2];

        float c = (fabsf(v0 - cen0) + fabsf(v1 - cen1) + fabsf(v2 - cen2))
                  * (1.0f / 3.0f);
        scl[n * 128 + tid] = c;
        total += c;
    }
    __syncwarp();

    // ---- angular 3x3 gaussian (edge-clamped) via rolling 3 rows
    const int ep = epoch ? *epoch : 1;
    float key[NV];
    {
        float r0[7], r1[7], r2[7];
#pragma unroll
        for (int v = 0; v < 7; ++v) { r1[v] = scl[v * 128 + tid]; r0[v] = r1[v]; }
#pragma unroll
        for (int v = 0; v < 7; ++v) r2[v] = scl[(7 + v) * 128 + tid];

        const float G00 = 0.0751f, G01 = 0.1238f, G11 = 0.2042f;
#pragma unroll
        for (int u = 0; u < 7; ++u) {
#pragma unroll
            for (int v = 0; v < 7; ++v) {
                const int vm = (v > 0) ? v - 1 : 0;
                const int vp = (v < 6) ? v + 1 : 6;
                key[u * 7 + v] =
                    G00 * (r0[vm] + r0[vp] + r2[vm] + r2[vp]) +
                    G01 * (r0[v] + r2[v] + r1[vm] + r1[vp]) +
                    G11 * r1[v];
            }
            // shift rows
#pragma unroll
            for (int v = 0; v < 7; ++v) { r0[v] = r1[v]; r1[v] = r2[v]; }
            const int nxt = (u + 2 < 7) ? u + 2 : 6;
#pragma unroll
            for (int v = 0; v < 7; ++v) r2[v] = scl[(nxt * 7 + v) * 128 + tid];
        }
        if (ep <= 0) {
#pragma unroll
            for (int n = 0; n < NV; ++n) key[n] = scl[n * 128 + tid];
        }
    }

    // ---- rank-count top-m exclusion
    // mask excludes ranks < m, m = floor(y)+1; rank(n) = #{j : key[j] > key[n]}
    // (stable tie-break by index)
    const float yv = y[(b * HH + py) * WW + px];
    int m = (int)floorf(yv) + 1;
    m = min(max(m, 0), NV);

    float topsum = 0.0f;
#pragma unroll
    for (int n = 0; n < NV; ++n) {
        int cnt = 0;
#pragma unroll
        for (int j = 0; j < NV; ++j) {
            if (j < n)       cnt += (key[j] >= key[n]);
            else if (j > n)  cnt += (key[j] >  key[n]);
        }
        if (cnt < m) topsum += scl[n * 128 + tid];
    }

    float contrib = (total - topsum) * ((float)NV / ((float)NV - yv));

    // ---- block reduction -> per-block slots
#pragma unroll
    for (int o = 16; o > 0; o >>= 1) {
        contrib += __shfl_down_sync(0xFFFFFFFFu, contrib, o);
        gx_t    += __shfl_down_sync(0xFFFFFFFFu, gx_t, o);
        gy_t    += __shfl_down_sync(0xFFFFFFFFu, gy_t, o);
    }
    __shared__ float wcl[4], wgx[4], wgy[4];
    const int lane = tid & 31, wid = tid >> 5;
    if (lane == 0) { wcl[wid] = contrib; wgx[wid] = gx_t; wgy[wid] = gy_t; }
    __syncthreads();
    if (tid == 0) {
        g_cl_part[blockIdx.x] = wcl[0] + wcl[1] + wcl[2] + wcl[3];
        g_gx_part[blockIdx.x] = wgx[0] + wgx[1] + wgx[2] + wgx[3];
        g_gy_part[blockIdx.x] = wgy[0] + wgy[1] + wgy[2] + wgy[3];
    }
}

// ---------------------------------------------------------------------------
// Finalize: sum 1800 slots x3 in double, combine.
// ---------------------------------------------------------------------------
__global__ __launch_bounds__(256)
void finalize_kernel(float* __restrict__ out)
{
    double scl_ = 0.0, sgx = 0.0, sgy = 0.0;
    for (int i = threadIdx.x; i < NBLOCKS; i += 256) {
        scl_ += (double)g_cl_part[i];
        sgx  += (double)g_gx_part[i];
        sgy  += (double)g_gy_part[i];
    }
#pragma unroll
    for (int o = 16; o > 0; o >>= 1) {
        scl_ += __shfl_down_sync(0xFFFFFFFFu, scl_, o);
        sgx  += __shfl_down_sync(0xFFFFFFFFu, sgx, o);
        sgy  += __shfl_down_sync(0xFFFFFFFFu, sgy, o);
    }
    __shared__ double a[8], bx[8], by[8];
    const int lane = threadIdx.x & 31, wid = threadIdx.x >> 5;
    if (lane == 0) { a[wid] = scl_; bx[wid] = sgx; by[wid] = sgy; }
    __syncthreads();
    if (threadIdx.x == 0) {
        double tc = 0, tx = 0, ty = 0;
        for (int i = 0; i < 8; ++i) { tc += a[i]; tx += bx[i]; ty += by[i]; }
        const double cl_mean = tc / (double)((size_t)BB * NV * CH * CW);
        const double lx = tx / (double)(BB * CH * (CW - 1));
        const double ly = ty / (double)(BB * (CH - 1) * CW);
        out[0] = (float)(cl_mean + 0.1 * 0.5 * (lx + ly));
    }
}

extern "C" void kernel_launch(void* const* d_in, const int* in_sizes, int n_in,
                              void* d_out, int out_size)
{
    const float* pred  = (const float*)d_in[0];
    const float* x     = (const float*)d_in[1];
    const float* y     = (const float*)d_in[2];
    const int*   epoch = (n_in > 3) ? (const int*)d_in[3] : nullptr;
    float* out = (float*)d_out;

    // 3 dummy launches so the main kernel is my launch #4 — the slot ncu's
    // fixed "-s 5 -c 1" capture lands on (observed: harness contributes 2
    // launches before ours). Diagnostic; removed once profiled.
    dummy_kernel<<<1, 32>>>();
    dummy_kernel<<<1, 32>>>();
    dummy_kernel<<<1, 32>>>();
    color_kernel<<<NBLOCKS, 128>>>(pred, x, y, epoch);
    finalize_kernel<<<1, 256>>>(out);
}

// round 8
// speedup vs baseline: 1.2632x; 1.2632x over previous
#include <cuda_runtime.h>
#include <math.h>

#define ANG   7
#define NV    49
#define HH    256
#define WW    256
#define BB    4
#define CROPP 8
#define CH    (HH - 2*CROPP)   // 240
#define CW    (WW - 2*CROPP)   // 240
#define HW3   (HH*WW*3)
#define VIEW_STRIDE HW3
#define BATCH_STRIDE (NV*HW3)
#define NBLOCKS 1800
#define NPIX (BB*CH*CW)        // 230400

__device__ float g_scratch[NV * NPIX];   // cl values, [n][pixel], 45 MB
__device__ float g_cl_part[NBLOCKS];
__device__ float g_gx_part[NBLOCKS];
__device__ float g_gy_part[NBLOCKS];
__device__ int   g_dummy;

__global__ void dummy_kernel() {
    if (threadIdx.x == 0 && blockIdx.x == 0) g_dummy = 0;
}

// ---------------------------------------------------------------------------
// Phase 1: bilinear warp of 49 views -> cl[n][pixel] in global scratch.
// Register-light so the scattered-load phase runs at high occupancy.
// ---------------------------------------------------------------------------
__global__ __launch_bounds__(128, 6)
void warp_kernel(const float* __restrict__ pred, const float* __restrict__ x)
{
    const int tid = threadIdx.x;
    const int idx = blockIdx.x * 128 + tid;        // exact grid
    const int px  = (idx % CW) + CROPP;
    const int py  = ((idx / CW) % CH) + CROPP;
    const int b   = idx / (CH * CW);

    const float p = pred[(b * HH + py) * WW + px];
    const float* xb = x + (size_t)b * BATCH_STRIDE;

    const float* Icen = xb + 24 * VIEW_STRIDE;
    const int co = py * (WW * 3) + px * 3;
    const float cen0 = Icen[co + 0];
    const float cen1 = Icen[co + 1];
    const float cen2 = Icen[co + 2];

    // x-side tables (7 offsets, shared by all du)
    float tbv[7]; int xo0[7], xo1[7];
#pragma unroll
    for (int k = 0; k < 7; ++k) {
        float cx = fminf(fmaxf((float)px + p * (float)(k - 3), 0.0f), (float)(WW - 1));
        float fx = floorf(cx);
        int   x0 = (int)fx;
        tbv[k] = cx - fx;
        xo0[k] = x0 * 3;
        xo1[k] = min(x0 + 1, WW - 1) * 3;
    }

#pragma unroll
    for (int du = 0; du < 7; ++du) {
        float cy = fminf(fmaxf((float)py + p * (float)(du - 3), 0.0f), (float)(HH - 1));
        float fy = floorf(cy);
        int   y0 = (int)fy;
        const float ty  = cy - fy;
        const int   yo0 = y0 * (WW * 3);
        const int   yo1 = min(y0 + 1, HH - 1) * (WW * 3);
#pragma unroll
        for (int dv = 0; dv < 7; ++dv) {
            const int n = du * 7 + dv;
            const float* base = xb + n * VIEW_STRIDE;
            const float* p00 = base + yo0 + xo0[dv];
            const float* p01 = base + yo0 + xo1[dv];
            const float* p10 = base + yo1 + xo0[dv];
            const float* p11 = base + yo1 + xo1[dv];
            const float tx = tbv[dv];
            const float w00 = (1.0f - ty) * (1.0f - tx);
            const float w01 = (1.0f - ty) * tx;
            const float w10 = ty * (1.0f - tx);
            const float w11 = ty * tx;

            float v0 = w00 * p00[0] + w01 * p01[0] + w10 * p10[0] + w11 * p11[0];
            float v1 = w00 * p00[1] + w01 * p01[1] + w10 * p10[1] + w11 * p11[1];
            float v2 = w00 * p00[2] + w01 * p01[2] + w10 * p10[2] + w11 * p11[2];

            float c = (fabsf(v0 - cen0) + fabsf(v1 - cen1) + fabsf(v2 - cen2))
                      * (1.0f / 3.0f);
            g_scratch[n * NPIX + idx] = c;
        }
    }
}

// Scatter-accumulate one source cl value into the 3x3 edge-clamped gaussian.
// a, bv are compile-time constants at every call site -> weights fold.
__device__ __forceinline__ void scatter_add(float* key, int a, int bv, float c)
{
#pragma unroll
    for (int u = 0; u < 7; ++u) {
#pragma unroll
        for (int v = 0; v < 7; ++v) {
            float w = 0.0f;
#pragma unroll
            for (int i = -1; i <= 1; ++i) {
#pragma unroll
                for (int j = -1; j <= 1; ++j) {
                    const int uu = min(max(u + i, 0), 6);
                    const int vv = min(max(v + j, 0), 6);
                    if (uu == a && vv == bv)
                        w += ((i == 0 && j == 0) ? 0.2042f
                             : ((i == 0 || j == 0) ? 0.1238f : 0.0751f));
                }
            }
            if (w != 0.0f) key[u * 7 + v] += w * c;
        }
    }
}

// ---------------------------------------------------------------------------
// Phase 2: gaussian keys (scatter), bitonic sort -> m-th largest threshold,
// threshold pass for topsum; fused edge-aware smoothness; block partials.
// ---------------------------------------------------------------------------
__global__ __launch_bounds__(128, 5)
void select_kernel(const float* __restrict__ pred,
                   const float* __restrict__ x,
                   const float* __restrict__ y,
                   const int*   __restrict__ epoch)
{
    const int tid = threadIdx.x;
    const int idx = blockIdx.x * 128 + tid;
    const int px  = (idx % CW) + CROPP;
    const int py  = ((idx / CW) % CH) + CROPP;
    const int b   = idx / (CH * CW);

    const float* pr = pred + b * HH * WW;
    const float  p  = pr[py * WW + px];

    // ---- fused edge-aware smoothness (center view + pred)
    float gx_t = 0.0f, gy_t = 0.0f;
    {
        const float* Icen = x + (size_t)b * BATCH_STRIDE + 24 * VIEW_STRIDE;
        const int co = py * (WW * 3) + px * 3;
        const float c0 = Icen[co], c1 = Icen[co + 1], c2 = Icen[co + 2];
        if (px - CROPP < CW - 1) {
            float a = fabsf(Icen[co + 3] - c0) + fabsf(Icen[co + 4] - c1)
                    + fabsf(Icen[co + 5] - c2);
            gx_t = expf(-150.0f * a * (1.0f / 3.0f))
                 * fabsf(pr[py * WW + px + 1] - p);
        }
        if (py - CROPP < CH - 1) {
            float a = fabsf(Icen[co + WW * 3 + 0] - c0)
                    + fabsf(Icen[co + WW * 3 + 1] - c1)
                    + fabsf(Icen[co + WW * 3 + 2] - c2);
            gy_t = expf(-150.0f * a * (1.0f / 3.0f))
                 * fabsf(pr[(py + 1) * WW + px] - p);
        }
    }

    const int ep = epoch ? *epoch : 1;

    // ---- pass A: load cl, total, gaussian keys (scatter), pad to 64
    float key[64];
#pragma unroll
    for (int n = 0; n < NV; ++n) key[n] = 0.0f;
#pragma unroll
    for (int n = NV; n < 64; ++n) key[n] = -1.0f;   // cl >= 0, pads sink

    float total = 0.0f;
    if (ep > 0) {
#pragma unroll
        for (int a = 0; a < 7; ++a) {
#pragma unroll
            for (int bv = 0; bv < 7; ++bv) {
                float c = g_scratch[(a * 7 + bv) * NPIX + idx];
                total += c;
                scatter_add(key, a, bv, c);
            }
        }
    } else {
#pragma unroll
        for (int n = 0; n < NV; ++n) {
            float c = g_scratch[n * NPIX + idx];
            total += c;
            key[n] = c;
        }
    }

    // ---- bitonic sort, descending (fully unrolled, 672 CAS)
#pragma unroll
    for (int k = 2; k <= 64; k <<= 1) {
#pragma unroll
        for (int j = k >> 1; j > 0; j >>= 1) {
#pragma unroll
            for (int i = 0; i < 64; ++i) {
                const int l = i ^ j;
                if (l > i) {
                    const bool desc = ((i & k) == 0);
                    float av = key[i], bq = key[l];
                    float hi = fmaxf(av, bq), lo = fminf(av, bq);
                    key[i] = desc ? hi : lo;
                    key[l] = desc ? lo : hi;
                }
            }
        }
    }

    // ---- tau = m-th largest key (index m-1), m = floor(y)+1 in [1, 49]
    const float yv = y[(b * HH + py) * WW + px];
    int m = (int)floorf(yv) + 1;
    m = min(max(m, 1), NV);
    float tau = key[0];
#pragma unroll
    for (int i = 1; i < NV; ++i)
        if (m == i + 1) tau = key[i];

    // ---- pass B: recompute keys (bit-identical scatter), threshold topsum
    float key2[NV];
    float topsum = 0.0f;
    if (ep > 0) {
#pragma unroll
        for (int n = 0; n < NV; ++n) key2[n] = 0.0f;
#pragma unroll
        for (int a = 0; a < 7; ++a) {
#pragma unroll
            for (int bv = 0; bv < 7; ++bv) {
                float c = g_scratch[(a * 7 + bv) * NPIX + idx];
                scatter_add(key2, a, bv, c);
            }
        }
#pragma unroll
        for (int n = 0; n < NV; ++n) {
            float c = g_scratch[n * NPIX + idx];
            if (key2[n] >= tau) topsum += c;
        }
    } else {
#pragma unroll
        for (int n = 0; n < NV; ++n) {
            float c = g_scratch[n * NPIX + idx];
            if (c >= tau) topsum += c;
        }
    }

    float contrib = (total - topsum) * ((float)NV / ((float)NV - yv));

    // ---- block reduction -> per-block slots
#pragma unroll
    for (int o = 16; o > 0; o >>= 1) {
        contrib += __shfl_down_sync(0xFFFFFFFFu, contrib, o);
        gx_t    += __shfl_down_sync(0xFFFFFFFFu, gx_t, o);
        gy_t    += __shfl_down_sync(0xFFFFFFFFu, gy_t, o);
    }
    __shared__ float wcl[4], wgx[4], wgy[4];
    const int lane = tid & 31, wid = tid >> 5;
    if (lane == 0) { wcl[wid] = contrib; wgx[wid] = gx_t; wgy[wid] = gy_t; }
    __syncthreads();
    if (tid == 0) {
        g_cl_part[blockIdx.x] = wcl[0] + wcl[1] + wcl[2] + wcl[3];
        g_gx_part[blockIdx.x] = wgx[0] + wgx[1] + wgx[2] + wgx[3];
        g_gy_part[blockIdx.x] = wgy[0] + wgy[1] + wgy[2] + wgy[3];
    }
}

__global__ __launch_bounds__(256)
void finalize_kernel(float* __restrict__ out)
{
    double scl_ = 0.0, sgx = 0.0, sgy = 0.0;
    for (int i = threadIdx.x; i < NBLOCKS; i += 256) {
        scl_ += (double)g_cl_part[i];
        sgx  += (double)g_gx_part[i];
        sgy  += (double)g_gy_part[i];
    }
#pragma unroll
    for (int o = 16; o > 0; o >>= 1) {
        scl_ += __shfl_down_sync(0xFFFFFFFFu, scl_, o);
        sgx  += __shfl_down_sync(0xFFFFFFFFu, sgx, o);
        sgy  += __shfl_down_sync(0xFFFFFFFFu, sgy, o);
    }
    __shared__ double a[8], bx[8], by[8];
    const int lane = threadIdx.x & 31, wid = threadIdx.x >> 5;
    if (lane == 0) { a[wid] = scl_; bx[wid] = sgx; by[wid] = sgy; }
    __syncthreads();
    if (threadIdx.x == 0) {
        double tc = 0, tx = 0, ty = 0;
        for (int i = 0; i < 8; ++i) { tc += a[i]; tx += bx[i]; ty += by[i]; }
        const double cl_mean = tc / (double)((size_t)BB * NV * CH * CW);
        const double lx = tx / (double)(BB * CH * (CW - 1));
        const double ly = ty / (double)(BB * (CH - 1) * CW);
        out[0] = (float)(cl_mean + 0.1 * 0.5 * (lx + ly));
    }
}

extern "C" void kernel_launch(void* const* d_in, const int* in_sizes, int n_in,
                              void* d_out, int out_size)
{
    const float* pred  = (const float*)d_in[0];
    const float* x     = (const float*)d_in[1];
    const float* y     = (const float*)d_in[2];
    const int*   epoch = (n_in > 3) ? (const int*)d_in[3] : nullptr;
    float* out = (float*)d_out;

    // 3 dummies so warp_kernel lands in ncu's fixed capture slot (my launch #4).
    dummy_kernel<<<1, 32>>>();
    dummy_kernel<<<1, 32>>>();
    dummy_kernel<<<1, 32>>>();
    warp_kernel<<<NBLOCKS, 128>>>(pred, x);
    select_kernel<<<NBLOCKS, 128>>>(pred, x, y, epoch);
    finalize_kernel<<<1, 256>>>(out);
}

// round 9
// speedup vs baseline: 1.2758x; 1.0099x over previous
#include <cuda_runtime.h>
#include <math.h>

#define ANG   7
#define NV    49
#define HH    256
#define WW    256
#define BB    4
#define CROPP 8
#define CH    (HH - 2*CROPP)   // 240
#define CW    (WW - 2*CROPP)   // 240
#define HW3   (HH*WW*3)
#define VIEW_STRIDE HW3
#define BATCH_STRIDE (NV*HW3)
#define NBLOCKS 1800
#define NPIX (BB*CH*CW)        // 230400

__device__ float g_scratch[NV * NPIX];   // cl values, [n][pixel], 45 MB
__device__ float g_cl_part[NBLOCKS];
__device__ float g_gx_part[NBLOCKS];
__device__ float g_gy_part[NBLOCKS];
__device__ int   g_dummy;

__global__ void dummy_kernel() {
    if (threadIdx.x == 0 && blockIdx.x == 0) g_dummy = 0;
}

// ---------------------------------------------------------------------------
// Phase 1: bilinear warp of 49 views -> cl[n][pixel] in global scratch.
// Loads per tap-row collapsed into 1-3 aligned float4 loads + SEL extraction:
// the 6 floats needed per row (x0,x1 taps x RGB) span <=24B at offset x0*12.
// ---------------------------------------------------------------------------
__global__ __launch_bounds__(128, 5)
void warp_kernel(const float* __restrict__ pred, const float* __restrict__ x)
{
    const int tid = threadIdx.x;
    const int idx = blockIdx.x * 128 + tid;        // exact grid
    const int px  = (idx % CW) + CROPP;
    const int py  = ((idx / CW) % CH) + CROPP;
    const int b   = idx / (CH * CW);

    const float p = pred[(b * HH + py) * WW + px];
    const float* xb = x + (size_t)b * BATCH_STRIDE;
    const float4* xb4 = (const float4*)xb;

    const float* Icen = xb + 24 * VIEW_STRIDE;
    const int co = py * (WW * 3) + px * 3;
    const float cen0 = Icen[co + 0];
    const float cen1 = Icen[co + 1];
    const float cen2 = Icen[co + 2];

    // ---- per-dv x tables: aligned float4 window + in-window offsets
    int   qx4[7], oo[7], o1v[7];
    float txv[7];
#pragma unroll
    for (int k = 0; k < 7; ++k) {
        float cx = fminf(fmaxf((float)px + p * (float)(k - 3), 0.0f), 255.0f);
        float fx = floorf(cx);
        int   x0 = (int)fx;
        int   x1 = min(x0 + 1, 255);
        txv[k] = cx - fx;
        const int f = x0 * 3;          // first needed float within row
        const int q = f & ~3;          // aligned float4 start
        qx4[k] = q >> 2;               // float4 index within row
        oo[k]  = f - q;                // 0..3
        o1v[k] = (f - q) + 3 * (x1 - x0);  // o (clamped) or o+3
    }

#pragma unroll
    for (int du = 0; du < 7; ++du) {
        float cy = fminf(fmaxf((float)py + p * (float)(du - 3), 0.0f), 255.0f);
        float fy = floorf(cy);
        int   y0 = (int)fy;
        const float ty = cy - fy;
        const int ra4 = y0 * (WW * 3 / 4);                 // row y0, float4 units
        const int rb4 = min(y0 + 1, 255) * (WW * 3 / 4);   // row y1

#pragma unroll
        for (int dv = 0; dv < 7; ++dv) {
            const int n = du * 7 + dv;
            const int vbase = n * (VIEW_STRIDE / 4);
            const float4* pa = xb4 + vbase + ra4 + qx4[dv];
            const float4* pb = xb4 + vbase + rb4 + qx4[dv];

            const int o  = oo[dv];
            const int oq = o1v[dv];
            const bool po1 = (o >= 1), po2 = (o >= 2), po3 = (o == 3);
            const bool c1 = (oq >= 2);        // need 2nd float4
            const bool c2 = (oq == 6);        // need 3rd float4
            const bool clm = (oq == o);       // x1 clamped to x0

            float4 A0 = __ldg(pa);
            float4 B0 = __ldg(pb);
            float4 A1, A2, B1, B2;
            if (c1) { A1 = __ldg(pa + 1); B1 = __ldg(pb + 1); }
            if (c2) { A2 = __ldg(pa + 2); B2 = __ldg(pb + 2); }

            // extract a[o..o+2] (x0 tap) and a[o+3..o+5] (x1 tap) per row
            float au0 = po2 ? (po3 ? A0.w : A0.z) : (po1 ? A0.y : A0.x);
            float au1 = po2 ? (po3 ? A1.x : A0.w) : (po1 ? A0.z : A0.y);
            float au2 = po2 ? (po3 ? A1.y : A1.x) : (po1 ? A0.w : A0.z);
            float at0 = po2 ? (po3 ? A1.z : A1.y) : (po1 ? A1.x : A0.w);
            float at1 = po2 ? (po3 ? A1.w : A1.z) : (po1 ? A1.y : A1.x);
            float at2 = po2 ? (po3 ? A2.x : A1.w) : (po1 ? A1.z : A1.y);
            if (clm) { at0 = au0; at1 = au1; at2 = au2; }

            float bu0 = po2 ? (po3 ? B0.w : B0.z) : (po1 ? B0.y : B0.x);
            float bu1 = po2 ? (po3 ? B1.x : B0.w) : (po1 ? B0.z : B0.y);
            float bu2 = po2 ? (po3 ? B1.y : B1.x) : (po1 ? B0.w : B0.z);
            float bt0 = po2 ? (po3 ? B1.z : B1.y) : (po1 ? B1.x : B0.w);
            float bt1 = po2 ? (po3 ? B1.w : B1.z) : (po1 ? B1.y : B1.x);
            float bt2 = po2 ? (po3 ? B2.x : B1.w) : (po1 ? B1.z : B1.y);
            if (clm) { bt0 = bu0; bt1 = bu1; bt2 = bu2; }

            // bilinear: lerp x within each row, then lerp y
            const float tx = txv[dv];
            float r0 = au0 + tx * (at0 - au0);
            float r1 = au1 + tx * (at1 - au1);
            float r2 = au2 + tx * (at2 - au2);
            float s0 = bu0 + tx * (bt0 - bu0);
            float s1 = bu1 + tx * (bt1 - bu1);
            float s2 = bu2 + tx * (bt2 - bu2);
            float v0 = r0 + ty * (s0 - r0);
            float v1 = r1 + ty * (s1 - r1);
            float v2 = r2 + ty * (s2 - r2);

            float c = (fabsf(v0 - cen0) + fabsf(v1 - cen1) + fabsf(v2 - cen2))
                      * (1.0f / 3.0f);
            g_scratch[n * NPIX + idx] = c;
        }
    }
}

// Scatter-accumulate one source cl value into the 3x3 edge-clamped gaussian.
__device__ __forceinline__ void scatter_add(float* key, int a, int bv, float c)
{
#pragma unroll
    for (int u = 0; u < 7; ++u) {
#pragma unroll
        for (int v = 0; v < 7; ++v) {
            float w = 0.0f;
#pragma unroll
            for (int i = -1; i <= 1; ++i) {
#pragma unroll
                for (int j = -1; j <= 1; ++j) {
                    const int uu = min(max(u + i, 0), 6);
                    const int vv = min(max(v + j, 0), 6);
                    if (uu == a && vv == bv)
                        w += ((i == 0 && j == 0) ? 0.2042f
                             : ((i == 0 || j == 0) ? 0.1238f : 0.0751f));
                }
            }
            if (w != 0.0f) key[u * 7 + v] += w * c;
        }
    }
}

// ---------------------------------------------------------------------------
// Phase 2: gaussian keys (scatter), bitonic sort -> m-th largest threshold,
// threshold pass for topsum; fused edge-aware smoothness; block partials.
// ---------------------------------------------------------------------------
__global__ __launch_bounds__(128, 5)
void select_kernel(const float* __restrict__ pred,
                   const float* __restrict__ x,
                   const float* __restrict__ y,
                   const int*   __restrict__ epoch)
{
    const int tid = threadIdx.x;
    const int idx = blockIdx.x * 128 + tid;
    const int px  = (idx % CW) + CROPP;
    const int py  = ((idx / CW) % CH) + CROPP;
    const int b   = idx / (CH * CW);

    const float* pr = pred + b * HH * WW;
    const float  p  = pr[py * WW + px];

    // ---- fused edge-aware smoothness (center view + pred)
    float gx_t = 0.0f, gy_t = 0.0f;
    {
        const float* Icen = x + (size_t)b * BATCH_STRIDE + 24 * VIEW_STRIDE;
        const int co = py * (WW * 3) + px * 3;
        const float c0 = Icen[co], c1 = Icen[co + 1], c2 = Icen[co + 2];
        if (px - CROPP < CW - 1) {
            float a = fabsf(Icen[co + 3] - c0) + fabsf(Icen[co + 4] - c1)
                    + fabsf(Icen[co + 5] - c2);
            gx_t = expf(-150.0f * a * (1.0f / 3.0f))
                 * fabsf(pr[py * WW + px + 1] - p);
        }
        if (py - CROPP < CH - 1) {
            float a = fabsf(Icen[co + WW * 3 + 0] - c0)
                    + fabsf(Icen[co + WW * 3 + 1] - c1)
                    + fabsf(Icen[co + WW * 3 + 2] - c2);
            gy_t = expf(-150.0f * a * (1.0f / 3.0f))
                 * fabsf(pr[(py + 1) * WW + px] - p);
        }
    }

    const int ep = epoch ? *epoch : 1;

    // ---- pass A: load cl, total, gaussian keys (scatter), pad to 64
    float key[64];
#pragma unroll
    for (int n = 0; n < NV; ++n) key[n] = 0.0f;
#pragma unroll
    for (int n = NV; n < 64; ++n) key[n] = -1.0f;   // cl >= 0, pads sink

    float total = 0.0f;
    if (ep > 0) {
#pragma unroll
        for (int a = 0; a < 7; ++a) {
#pragma unroll
            for (int bv = 0; bv < 7; ++bv) {
                float c = g_scratch[(a * 7 + bv) * NPIX + idx];
                total += c;
                scatter_add(key, a, bv, c);
            }
        }
    } else {
#pragma unroll
        for (int n = 0; n < NV; ++n) {
            float c = g_scratch[n * NPIX + idx];
            total += c;
            key[n] = c;
        }
    }

    // ---- bitonic sort, descending (fully unrolled, 672 CAS)
#pragma unroll
    for (int k = 2; k <= 64; k <<= 1) {
#pragma unroll
        for (int j = k >> 1; j > 0; j >>= 1) {
#pragma unroll
            for (int i = 0; i < 64; ++i) {
                const int l = i ^ j;
                if (l > i) {
                    const bool desc = ((i & k) == 0);
                    float av = key[i], bq = key[l];
                    float hi = fmaxf(av, bq), lo = fminf(av, bq);
                    key[i] = desc ? hi : lo;
                    key[l] = desc ? lo : hi;
                }
            }
        }
    }

    // ---- tau = m-th largest key (index m-1), m = floor(y)+1 in [1, 49]
    const float yv = y[(b * HH + py) * WW + px];
    int m = (int)floorf(yv) + 1;
    m = min(max(m, 1), NV);
    float tau = key[0];
#pragma unroll
    for (int i = 1; i < NV; ++i)
        if (m == i + 1) tau = key[i];

    // ---- pass B: recompute keys (bit-identical scatter), threshold topsum
    float key2[NV];
    float topsum = 0.0f;
    if (ep > 0) {
#pragma unroll
        for (int n = 0; n < NV; ++n) key2[n] = 0.0f;
#pragma unroll
        for (int a = 0; a < 7; ++a) {
#pragma unroll
            for (int bv = 0; bv < 7; ++bv) {
                float c = g_scratch[(a * 7 + bv) * NPIX + idx];
                scatter_add(key2, a, bv, c);
            }
        }
#pragma unroll
        for (int n = 0; n < NV; ++n) {
            float c = g_scratch[n * NPIX + idx];
            if (key2[n] >= tau) topsum += c;
        }
    } else {
#pragma unroll
        for (int n = 0; n < NV; ++n) {
            float c = g_scratch[n * NPIX + idx];
            if (c >= tau) topsum += c;
        }
    }

    float contrib = (total - topsum) * ((float)NV / ((float)NV - yv));

    // ---- block reduction -> per-block slots
#pragma unroll
    for (int o = 16; o > 0; o >>= 1) {
        contrib += __shfl_down_sync(0xFFFFFFFFu, contrib, o);
        gx_t    += __shfl_down_sync(0xFFFFFFFFu, gx_t, o);
        gy_t    += __shfl_down_sync(0xFFFFFFFFu, gy_t, o);
    }
    __shared__ float wcl[4], wgx[4], wgy[4];
    const int lane = tid & 31, wid = tid >> 5;
    if (lane == 0) { wcl[wid] = contrib; wgx[wid] = gx_t; wgy[wid] = gy_t; }
    __syncthreads();
    if (tid == 0) {
        g_cl_part[blockIdx.x] = wcl[0] + wcl[1] + wcl[2] + wcl[3];
        g_gx_part[blockIdx.x] = wgx[0] + wgx[1] + wgx[2] + wgx[3];
        g_gy_part[blockIdx.x] = wgy[0] + wgy[1] + wgy[2] + wgy[3];
    }
}

__global__ __launch_bounds__(256)
void finalize_kernel(float* __restrict__ out)
{
    double scl_ = 0.0, sgx = 0.0, sgy = 0.0;
    for (int i = threadIdx.x; i < NBLOCKS; i += 256) {
        scl_ += (double)g_cl_part[i];
        sgx  += (double)g_gx_part[i];
        sgy  += (double)g_gy_part[i];
    }
#pragma unroll
    for (int o = 16; o > 0; o >>= 1) {
        scl_ += __shfl_down_sync(0xFFFFFFFFu, scl_, o);
        sgx  += __shfl_down_sync(0xFFFFFFFFu, sgx, o);
        sgy  += __shfl_down_sync(0xFFFFFFFFu, sgy, o);
    }
    __shared__ double a[8], bx[8], by[8];
    const int lane = threadIdx.x & 31, wid = threadIdx.x >> 5;
    if (lane == 0) { a[wid] = scl_; bx[wid] = sgx; by[wid] = sgy; }
    __syncthreads();
    if (threadIdx.x == 0) {
        double tc = 0, tx = 0, ty = 0;
        for (int i = 0; i < 8; ++i) { tc += a[i]; tx += bx[i]; ty += by[i]; }
        const double cl_mean = tc / (double)((size_t)BB * NV * CH * CW);
        const double lx = tx / (double)(BB * CH * (CW - 1));
        const double ly = ty / (double)(BB * (CH - 1) * CW);
        out[0] = (float)(cl_mean + 0.1 * 0.5 * (lx + ly));
    }
}

extern "C" void kernel_launch(void* const* d_in, const int* in_sizes, int n_in,
                              void* d_out, int out_size)
{
    const float* pred  = (const float*)d_in[0];
    const float* x     = (const float*)d_in[1];
    const float* y     = (const float*)d_in[2];
    const int*   epoch = (n_in > 3) ? (const int*)d_in[3] : nullptr;
    float* out = (float*)d_out;

    // 3 dummies so warp_kernel lands in ncu's fixed capture slot (my launch #4).
    dummy_kernel<<<1, 32>>>();
    dummy_kernel<<<1, 32>>>();
    dummy_kernel<<<1, 32>>>();
    warp_kernel<<<NBLOCKS, 128>>>(pred, x);
    select_kernel<<<NBLOCKS, 128>>>(pred, x, y, epoch);
    finalize_kernel<<<1, 256>>>(out);
}